// round 15
// baseline (speedup 1.0000x reference)
#include <cuda_runtime.h>
#include <cuda_bf16.h>
#include <cstdint>

#define BB 16
#define TT 4096
#define DD 512
#define LL 1024

#define TILE_M 128
#define TILE_N 128
#define KSTEP 16
#define NSTEPS 32                    // k-steps per N-tile (DD/16)
#define NTILES 32                    // TT/TILE_N
#define TOTSTEPS (NSTEPS * NTILES)   // 1024
#define NSTAGE 4

#define AH_OFF 0
#define AP_OFF 4096
#define BH_OFF 8192
#define BP_OFF 12288
#define STAGE_BYTES 16384
#define SMEM_TOTAL (NSTAGE * STAGE_BYTES)   // 65536

#define NTHREADS 512

// quantization scales: hi parts over +-6.0, lo residuals over +-0.015875
#define SH 21.166666f          // 127/6
#define SL 8000.0f
#define INV_SCALE (1.0f / (SH * SL))

// XOR swizzle: row stride 32B, 16B chunk index XORed with bit2 of row.
#define SWZ(row, chunk) ((uint32_t)((row) * 32 + (((chunk) ^ (((row) >> 2) & 1)) << 4)))

__device__ __nv_bfloat16 g_xh[BB * TT * DD];    // 64 MB  bf16 hi of x
__device__ __nv_bfloat16 g_qh[LL * DD];         // bf16 hi of q
__device__ int8_t g_xp[BB * TT * 1024];         // 64 MB  packed [xl8|xh8] per k16
__device__ int8_t g_qp[LL * 1024];              // packed [qh8|ql8] per k16
__device__ float g_y[BB * TT];

// ---------------- PTX helpers ----------------
__device__ __forceinline__ uint32_t smem_u32(const void* p) {
    uint32_t a;
    asm("{ .reg .u64 t; cvta.to.shared.u64 t, %1; cvt.u32.u64 %0, t; }" : "=r"(a) : "l"(p));
    return a;
}
__device__ __forceinline__ void cp16(uint32_t dst, const void* src) {
    asm volatile("cp.async.cg.shared.global [%0], [%1], 16;" :: "r"(dst), "l"(src));
}
#define CP_COMMIT() asm volatile("cp.async.commit_group;" ::: "memory")
#define CP_WAIT2()  asm volatile("cp.async.wait_group 2;" ::: "memory")

__device__ __forceinline__ void ldsm4(uint32_t* r, uint32_t addr) {
    asm volatile("ldmatrix.sync.aligned.m8n8.x4.shared.b16 {%0,%1,%2,%3}, [%4];"
                 : "=r"(r[0]), "=r"(r[1]), "=r"(r[2]), "=r"(r[3]) : "r"(addr));
}
__device__ __forceinline__ void mma16816(float* c, const uint32_t* a, uint32_t b0, uint32_t b1) {
    asm volatile(
        "mma.sync.aligned.m16n8k16.row.col.f32.bf16.bf16.f32 "
        "{%0,%1,%2,%3}, {%4,%5,%6,%7}, {%8,%9}, {%0,%1,%2,%3};"
        : "+f"(c[0]), "+f"(c[1]), "+f"(c[2]), "+f"(c[3])
        : "r"(a[0]), "r"(a[1]), "r"(a[2]), "r"(a[3]), "r"(b0), "r"(b1));
}
__device__ __forceinline__ void imma16832(int* c, const uint32_t* a, uint32_t b0, uint32_t b1) {
    asm volatile(
        "mma.sync.aligned.m16n8k32.row.col.s32.s8.s8.s32 "
        "{%0,%1,%2,%3}, {%4,%5,%6,%7}, {%8,%9}, {%0,%1,%2,%3};"
        : "+r"(c[0]), "+r"(c[1]), "+r"(c[2]), "+r"(c[3])
        : "r"(a[0]), "r"(a[1]), "r"(a[2]), "r"(a[3]), "r"(b0), "r"(b1));
}

// ---------------- precompute: bf16 hi, packed s8 [hi|lo] splits, y ----------------
__global__ __launch_bounds__(256) void prep_kernel(const float* __restrict__ x,
                                                   const float* __restrict__ q,
                                                   const float* __restrict__ fc_w) {
    int wrow = blockIdx.x * 8 + (threadIdx.x >> 5);
    int lane = threadIdx.x & 31;            // lane = k16 chunk index (DD/16 = 32)
    bool is_x = wrow < BB * TT;
    int lrow = is_x ? wrow : wrow - BB * TT;
    const float* src = (is_x ? x + (size_t)wrow * DD : q + (size_t)lrow * DD) + lane * 16;
    __nv_bfloat16* dh = (is_x ? g_xh + (size_t)wrow * DD : g_qh + (size_t)lrow * DD) + lane * 16;
    int8_t* dp = (is_x ? g_xp + (size_t)wrow * 1024 : g_qp + (size_t)lrow * 1024) + lane * 32;

    float v[16];
    *(float4*)(v + 0)  = ((const float4*)src)[0];
    *(float4*)(v + 4)  = ((const float4*)src)[1];
    *(float4*)(v + 8)  = ((const float4*)src)[2];
    *(float4*)(v + 12) = ((const float4*)src)[3];

    float s = 0.f;
    if (is_x) {
        const float4* w4 = (const float4*)(fc_w + lane * 16);
#pragma unroll
        for (int j = 0; j < 4; j++) {
            float4 w = w4[j];
            s += v[4 * j] * w.x + v[4 * j + 1] * w.y + v[4 * j + 2] * w.z + v[4 * j + 3] * w.w;
        }
    }

    uint32_t hbits[8];
    uint32_t hi8[4] = {0, 0, 0, 0}, lo8[4] = {0, 0, 0, 0};
#pragma unroll
    for (int j = 0; j < 16; j++) {
        __nv_bfloat16 h = __float2bfloat16(v[j]);
        float hf = __bfloat162float(h);
        float lo = v[j] - hf;
        if ((j & 1) == 0) hbits[j >> 1] = (uint32_t)(*(uint16_t*)&h);
        else              hbits[j >> 1] |= ((uint32_t)(*(uint16_t*)&h)) << 16;
        int hq = __float2int_rn(fminf(fmaxf(hf * SH, -127.f), 127.f));
        int lq = __float2int_rn(fminf(fmaxf(lo * SL, -127.f), 127.f));
        hi8[j >> 2] |= ((uint32_t)(hq & 0xff)) << ((j & 3) * 8);
        lo8[j >> 2] |= ((uint32_t)(lq & 0xff)) << ((j & 3) * 8);
    }
    ((uint4*)dh)[0] = make_uint4(hbits[0], hbits[1], hbits[2], hbits[3]);
    ((uint4*)dh)[1] = make_uint4(hbits[4], hbits[5], hbits[6], hbits[7]);
    // q packs [hi8 | lo8]; x packs [lo8 | hi8] so IMMA computes qh*xl + ql*xh
    uint4 p0 = is_x ? make_uint4(lo8[0], lo8[1], lo8[2], lo8[3])
                    : make_uint4(hi8[0], hi8[1], hi8[2], hi8[3]);
    uint4 p1 = is_x ? make_uint4(hi8[0], hi8[1], hi8[2], hi8[3])
                    : make_uint4(lo8[0], lo8[1], lo8[2], lo8[3]);
    ((uint4*)dp)[0] = p0;
    ((uint4*)dp)[1] = p1;

    if (is_x) {
#pragma unroll
        for (int o = 16; o; o >>= 1) s += __shfl_xor_sync(0xFFFFFFFFu, s, o);
        if (lane == 0) g_y[wrow] = s;
    }
}

// ---------------- main kernel: 16 warps (4Mx4N), warp tile 32x32, HMMA+IMMA ----------------
__global__ __launch_bounds__(NTHREADS, 1) void attn_kernel(const float* __restrict__ fc_b,
                                                           float* __restrict__ out) {
    extern __shared__ char smem[];
    uint32_t sb = smem_u32(smem);
    int tid = threadIdx.x, wid = tid >> 5, lane = tid & 31;
    int warpM = wid & 3, warpN = wid >> 2;      // 4 x 4 warps, warp tile 32x32
    int ltile = blockIdx.x, b = blockIdx.y;

    const float* yb = g_y + b * TT;

    // ---- per-thread load assignment: 2 x 16B chunks per stage ----
    // threads 0..255: AH + BH tiles; threads 256..511: AP + BP tiles
    int lc = tid & 255;
    int row = lc >> 1, half = lc & 1;
    bool pk = tid >= 256;
    uint32_t dstA = (pk ? AP_OFF : AH_OFF) + SWZ(row, half);
    uint32_t dstB = (pk ? BP_OFF : BH_OFF) + SWZ(row, half);
    const char* srcA = pk
        ? (const char*)(g_qp + (size_t)(ltile * TILE_M + row) * 1024 + half * 16)
        : (const char*)(g_qh + (size_t)(ltile * TILE_M + row) * DD + half * 8);
    const char* srcB = pk
        ? (const char*)(g_xp + ((size_t)b * TT + row) * 1024 + half * 16)
        : (const char*)(g_xh + ((size_t)b * TT + row) * DD + half * 8);

    // ---- ldmatrix lane offsets (tiles are 128 rows x 32B; same swizzle as bf16 k16) ----
    int a_r0 = warpM * 32 + (lane & 15);
    uint32_t a_off0 = SWZ(a_r0, lane >> 4);
    uint32_t a_off1 = SWZ(a_r0 + 16, lane >> 4);
    int q4 = lane >> 3;
    int b_r0 = warpN * 32 + ((q4 >> 1) & 1) * 8 + (lane & 7);
    uint32_t b_base = SWZ(b_r0, q4 & 1);

    // ---- accumulators + softmax state ----
    float acc_f[2][4][4];
    int   acc_i[2][4][4];
#pragma unroll
    for (int mt = 0; mt < 2; mt++)
#pragma unroll
        for (int g = 0; g < 4; g++)
#pragma unroll
            for (int i = 0; i < 4; i++) { acc_f[mt][g][i] = 0.f; acc_i[mt][g][i] = 0; }
    float m_run[2][2], Zp[2][2], Ap2[2][2];
#pragma unroll
    for (int mt = 0; mt < 2; mt++)
#pragma unroll
        for (int h = 0; h < 2; h++) {
            m_run[mt][h] = __int_as_float(0xff800000);
            Zp[mt][h] = 0.f; Ap2[mt][h] = 0.f;
        }

    auto issue = [&](int s) {
        int nt = s >> 5, kc = s & 31;
        uint32_t sbase = sb + (s & (NSTAGE - 1)) * STAGE_BYTES;
        cp16(sbase + dstA, srcA + kc * 32);
        cp16(sbase + dstB, srcB + (size_t)nt * 131072 + kc * 32);
    };

    for (int s = 0; s < NSTAGE - 1; s++) { issue(s); CP_COMMIT(); }

    for (int st = 0; st < TOTSTEPS; st++) {
        CP_WAIT2();
        __syncthreads();
        if (st + NSTAGE - 1 < TOTSTEPS) issue(st + NSTAGE - 1);
        CP_COMMIT();

        uint32_t sbase = sb + (st & (NSTAGE - 1)) * STAGE_BYTES;
        uint32_t Ah[2][4], Ap[2][4];
        ldsm4(Ah[0], sbase + AH_OFF + a_off0);
        ldsm4(Ah[1], sbase + AH_OFF + a_off1);
        ldsm4(Ap[0], sbase + AP_OFF + a_off0);
        ldsm4(Ap[1], sbase + AP_OFF + a_off1);
#pragma unroll
        for (int gp = 0; gp < 2; gp++) {
            uint32_t bh[4], bp[4];
            ldsm4(bh, sbase + BH_OFF + b_base + gp * 512);
            ldsm4(bp, sbase + BP_OFF + b_base + gp * 512);
#pragma unroll
            for (int g2 = 0; g2 < 2; g2++)
#pragma unroll
                for (int mt = 0; mt < 2; mt++) {
                    mma16816(acc_f[mt][gp * 2 + g2], Ah[mt], bh[2 * g2], bh[2 * g2 + 1]);
                    imma16832(acc_i[mt][gp * 2 + g2], Ap[mt], bp[2 * g2], bp[2 * g2 + 1]);
                }
        }

        if ((st & (NSTEPS - 1)) == NSTEPS - 1) {
            // ---- fold int correction into fp32 logits ----
#pragma unroll
            for (int mt = 0; mt < 2; mt++)
#pragma unroll
                for (int g = 0; g < 4; g++)
#pragma unroll
                    for (int i = 0; i < 4; i++) {
                        acc_f[mt][g][i] += (float)acc_i[mt][g][i] * INV_SCALE;
                        acc_i[mt][g][i] = 0;
                    }
            // ---- N-tile epilogue: online softmax (warp-local, 32-col slice) ----
            int nt = st >> 5;
#pragma unroll
            for (int mt = 0; mt < 2; mt++)
#pragma unroll
                for (int h = 0; h < 2; h++) {
                    float r = __int_as_float(0xff800000);
#pragma unroll
                    for (int g = 0; g < 4; g++)
                        r = fmaxf(r, fmaxf(acc_f[mt][g][2 * h], acc_f[mt][g][2 * h + 1]));
                    r = fmaxf(r, __shfl_xor_sync(0xFFFFFFFFu, r, 1));
                    r = fmaxf(r, __shfl_xor_sync(0xFFFFFFFFu, r, 2));
                    float mn = fmaxf(m_run[mt][h], r);
                    float sc = __expf(m_run[mt][h] - mn);
                    Zp[mt][h] *= sc; Ap2[mt][h] *= sc;
                    m_run[mt][h] = mn;
                }
            const float2* yrow = (const float2*)(yb + nt * TILE_N + warpN * 32);
#pragma unroll
            for (int g = 0; g < 4; g++) {
                float2 yv = __ldg(&yrow[g * 4 + (lane & 3)]);
#pragma unroll
                for (int mt = 0; mt < 2; mt++)
#pragma unroll
                    for (int h = 0; h < 2; h++) {
                        float e0 = __expf(acc_f[mt][g][2 * h]     - m_run[mt][h]);
                        float e1 = __expf(acc_f[mt][g][2 * h + 1] - m_run[mt][h]);
                        Zp[mt][h] += e0 + e1;
                        Ap2[mt][h] += e0 * yv.x + e1 * yv.y;
                        acc_f[mt][g][2 * h] = 0.f;
                        acc_f[mt][g][2 * h + 1] = 0.f;
                    }
            }
        }
    }

    // ---- final reductions: lanes within quad, then across 4 warpN warps ----
#pragma unroll
    for (int mt = 0; mt < 2; mt++)
#pragma unroll
        for (int h = 0; h < 2; h++) {
            float z = Zp[mt][h], a = Ap2[mt][h];
            z += __shfl_xor_sync(0xFFFFFFFFu, z, 1);
            z += __shfl_xor_sync(0xFFFFFFFFu, z, 2);
            a += __shfl_xor_sync(0xFFFFFFFFu, a, 1);
            a += __shfl_xor_sync(0xFFFFFFFFu, a, 2);
            Zp[mt][h] = z; Ap2[mt][h] = a;
        }
    __syncthreads();
    float* msm  = (float*)smem;            // 128*4 floats
    float* zsm  = msm + 512;
    float* asm2 = msm + 1024;
    if ((lane & 3) == 0) {
#pragma unroll
        for (int mt = 0; mt < 2; mt++)
#pragma unroll
            for (int h = 0; h < 2; h++) {
                int row2 = warpM * 32 + mt * 16 + (lane >> 2) + h * 8;
                int i = row2 * 4 + warpN;
                msm[i] = m_run[mt][h];
                zsm[i] = Zp[mt][h];
                asm2[i] = Ap2[mt][h];
            }
    }
    __syncthreads();
    if (tid < TILE_M) {
        float m0 = msm[tid * 4], m1 = msm[tid * 4 + 1];
        float m2 = msm[tid * 4 + 2], m3 = msm[tid * 4 + 3];
        float mstar = fmaxf(fmaxf(m0, m1), fmaxf(m2, m3));
        float e0 = __expf(m0 - mstar), e1 = __expf(m1 - mstar);
        float e2 = __expf(m2 - mstar), e3 = __expf(m3 - mstar);
        float Z = zsm[tid * 4] * e0 + zsm[tid * 4 + 1] * e1
                + zsm[tid * 4 + 2] * e2 + zsm[tid * 4 + 3] * e3;
        float A = asm2[tid * 4] * e0 + asm2[tid * 4 + 1] * e1
                + asm2[tid * 4 + 2] * e2 + asm2[tid * 4 + 3] * e3;
        out[(size_t)b * LL + ltile * TILE_M + tid] = A / Z + __ldg(fc_b);
    }
}

// ---------------- host ----------------
extern "C" void kernel_launch(void* const* d_in, const int* in_sizes, int n_in,
                              void* d_out, int out_size) {
    const float* x    = (const float*)d_in[0];
    const float* q    = (const float*)d_in[1];
    const float* fc_w = (const float*)d_in[2];
    const float* fc_b = (const float*)d_in[3];
    float* out = (float*)d_out;

    prep_kernel<<<(BB * TT + LL) / 8, 256>>>(x, q, fc_w);

    cudaFuncSetAttribute(attn_kernel, cudaFuncAttributeMaxDynamicSharedMemorySize, SMEM_TOTAL);
    attn_kernel<<<dim3(LL / TILE_M, BB), NTHREADS, SMEM_TOTAL>>>(fc_b, out);
}

// round 16
// speedup vs baseline: 2.1362x; 2.1362x over previous
#include <cuda_runtime.h>
#include <cuda_bf16.h>
#include <cstdint>

#define BB 16
#define TT 4096
#define DD 512
#define LL 1024

#define TILE_M 128
#define TILE_N 256
#define KSTEP 16
#define NSTEPS (DD / KSTEP)          // 32 k-steps per N-tile
#define NTILES (TT / TILE_N)         // 16
#define TOTSTEPS (NSTEPS * NTILES)   // 512
#define NSTAGE 5

#define A_HI_OFF 0
#define A_LO_OFF 4096
#define B_HI_OFF 8192
#define B_LO_OFF 16384
#define STAGE_BYTES 24576
#define SMEM_TOTAL (NSTAGE * STAGE_BYTES)   // 122880

#define NTHREADS 512

// XOR swizzle: row stride 32B, 16B chunk index XORed with bit2 of row.
#define SWZ(row, chunk) ((uint32_t)((row) * 32 + (((chunk) ^ (((row) >> 2) & 1)) << 4)))

__device__ __nv_bfloat16 g_xh[BB * TT * DD];   // 64 MB
__device__ __nv_bfloat16 g_xl[BB * TT * DD];   // 64 MB
__device__ __nv_bfloat16 g_qh[LL * DD];
__device__ __nv_bfloat16 g_ql[LL * DD];
__device__ float g_y[BB * TT];

// ---------------- PTX helpers ----------------
__device__ __forceinline__ uint32_t smem_u32(const void* p) {
    uint32_t a;
    asm("{ .reg .u64 t; cvta.to.shared.u64 t, %1; cvt.u32.u64 %0, t; }" : "=r"(a) : "l"(p));
    return a;
}
__device__ __forceinline__ void cp16(uint32_t dst, const void* src) {
    asm volatile("cp.async.cg.shared.global [%0], [%1], 16;" :: "r"(dst), "l"(src));
}
#define CP_COMMIT() asm volatile("cp.async.commit_group;" ::: "memory")
#define CP_WAIT3()  asm volatile("cp.async.wait_group 3;" ::: "memory")

__device__ __forceinline__ void ldsm4(uint32_t* r, uint32_t addr) {
    asm volatile("ldmatrix.sync.aligned.m8n8.x4.shared.b16 {%0,%1,%2,%3}, [%4];"
                 : "=r"(r[0]), "=r"(r[1]), "=r"(r[2]), "=r"(r[3]) : "r"(addr));
}
__device__ __forceinline__ void mma16816(float* c, const uint32_t* a, uint32_t b0, uint32_t b1) {
    asm volatile(
        "mma.sync.aligned.m16n8k16.row.col.f32.bf16.bf16.f32 "
        "{%0,%1,%2,%3}, {%4,%5,%6,%7}, {%8,%9}, {%0,%1,%2,%3};"
        : "+f"(c[0]), "+f"(c[1]), "+f"(c[2]), "+f"(c[3])
        : "r"(a[0]), "r"(a[1]), "r"(a[2]), "r"(a[3]), "r"(b0), "r"(b1));
}

// ---------------- precompute: bf16 hi/lo split of x and q, plus y ----------------
__global__ __launch_bounds__(256) void prep_kernel(const float* __restrict__ x,
                                                   const float* __restrict__ q,
                                                   const float* __restrict__ fc_w) {
    int wrow = blockIdx.x * 8 + (threadIdx.x >> 5);
    int lane = threadIdx.x & 31;
    bool is_x = wrow < BB * TT;
    const float* src = is_x ? (x + (size_t)wrow * DD)
                            : (q + (size_t)(wrow - BB * TT) * DD);
    __nv_bfloat16* dh = is_x ? (g_xh + (size_t)wrow * DD)
                             : (g_qh + (size_t)(wrow - BB * TT) * DD);
    __nv_bfloat16* dl = is_x ? (g_xl + (size_t)wrow * DD)
                             : (g_ql + (size_t)(wrow - BB * TT) * DD);
    float s = 0.f;
#pragma unroll
    for (int c = 0; c < 4; c++) {
        int idx = c * 128 + lane * 4;
        float4 v = *(const float4*)(src + idx);
        if (is_x) {
            float4 w = *(const float4*)(fc_w + idx);
            s += v.x * w.x + v.y * w.y + v.z * w.z + v.w * w.w;
        }
        __nv_bfloat16 hx = __float2bfloat16(v.x), hy = __float2bfloat16(v.y);
        __nv_bfloat16 hz = __float2bfloat16(v.z), hw = __float2bfloat16(v.w);
        __nv_bfloat162 h01, h23, l01, l23;
        h01.x = hx; h01.y = hy; h23.x = hz; h23.y = hw;
        l01.x = __float2bfloat16(v.x - __bfloat162float(hx));
        l01.y = __float2bfloat16(v.y - __bfloat162float(hy));
        l23.x = __float2bfloat16(v.z - __bfloat162float(hz));
        l23.y = __float2bfloat16(v.w - __bfloat162float(hw));
        uint2 ph = make_uint2(*(uint32_t*)&h01, *(uint32_t*)&h23);
        uint2 pl = make_uint2(*(uint32_t*)&l01, *(uint32_t*)&l23);
        *(uint2*)(dh + idx) = ph;
        *(uint2*)(dl + idx) = pl;
    }
    if (is_x) {
#pragma unroll
        for (int o = 16; o; o >>= 1) s += __shfl_xor_sync(0xFFFFFFFFu, s, o);
        if (lane == 0) g_y[wrow] = s;
    }
}

// ---------------- main kernel: 16 warps (4Mx4N), 5-stage pipe, deferred issue ----------------
__global__ __launch_bounds__(NTHREADS, 1) void attn_kernel(const float* __restrict__ fc_b,
                                                           float* __restrict__ out) {
    extern __shared__ char smem[];
    uint32_t sb = smem_u32(smem);
    int tid = threadIdx.x, wid = tid >> 5, lane = tid & 31;
    int warpM = wid & 3, warpN = wid >> 2;      // 4 x 4 warps
    int ltile = blockIdx.x, b = blockIdx.y;

    const __nv_bfloat16* qh = g_qh + (size_t)(ltile * TILE_M) * DD;
    const __nv_bfloat16* ql = g_ql + (size_t)(ltile * TILE_M) * DD;
    const __nv_bfloat16* xh = g_xh + (size_t)b * TT * DD;
    const __nv_bfloat16* xl = g_xl + (size_t)b * TT * DD;
    const float* yb = g_y + b * TT;

    // ---- per-thread load assignment: 1 A chunk + 2 B chunks (16B each), swizzled dst ----
    int ac = tid & 255;
    int a_row = ac >> 1, a_half = ac & 1;
    uint32_t a_dst = (tid < 256 ? A_HI_OFF : A_LO_OFF) + SWZ(a_row, a_half);
    const __nv_bfloat16* a_srcbase = (tid < 256 ? qh : ql) + (size_t)a_row * DD + a_half * 8;
    int b_row = tid >> 1, b_half = tid & 1;
    uint32_t b_dst = SWZ(b_row, b_half);
    size_t b_rowoff = (size_t)b_row * DD + b_half * 8;

    // ---- ldmatrix lane offsets ----
    int a_r0 = warpM * 32 + (lane & 15);
    uint32_t a_off0 = SWZ(a_r0, lane >> 4);
    uint32_t a_off1 = SWZ(a_r0 + 16, lane >> 4);
    int q4 = lane >> 3;
    int b_r0 = warpN * 64 + ((q4 >> 1) & 1) * 8 + (lane & 7);
    uint32_t b_base = SWZ(b_r0, q4 & 1);

    // ---- accumulators + softmax state ----
    float acc[2][8][4];
#pragma unroll
    for (int mt = 0; mt < 2; mt++)
#pragma unroll
        for (int g = 0; g < 8; g++)
#pragma unroll
            for (int i = 0; i < 4; i++) acc[mt][g][i] = 0.f;
    float m_run[2][2], Zp[2][2], Ap[2][2];
#pragma unroll
    for (int mt = 0; mt < 2; mt++)
#pragma unroll
        for (int h = 0; h < 2; h++) {
            m_run[mt][h] = __int_as_float(0xff800000);
            Zp[mt][h] = 0.f; Ap[mt][h] = 0.f;
        }

    // stage s lives in buffer s % NSTAGE
    auto issue = [&](int s) {
        int nt = s >> 5, kc = s & 31;
        int k0 = kc * KSTEP;
        uint32_t sbase = sb + (uint32_t)(s % NSTAGE) * STAGE_BYTES;
        cp16(sbase + a_dst, a_srcbase + k0);
        size_t bsrc = (size_t)(nt * TILE_N) * DD + k0 + b_rowoff;
        cp16(sbase + B_HI_OFF + b_dst, xh + bsrc);
        cp16(sbase + B_LO_OFF + b_dst, xl + bsrc);
    };

    for (int s = 0; s < NSTAGE - 1; s++) { issue(s); CP_COMMIT(); }

    for (int st = 0; st < TOTSTEPS; st++) {
        CP_WAIT3();
        __syncthreads();

        uint32_t sbase = sb + (uint32_t)(st % NSTAGE) * STAGE_BYTES;
        uint32_t Ah[2][4], Al[2][4];
        ldsm4(Ah[0], sbase + A_HI_OFF + a_off0);
        ldsm4(Ah[1], sbase + A_HI_OFF + a_off1);
        ldsm4(Al[0], sbase + A_LO_OFF + a_off0);
        ldsm4(Al[1], sbase + A_LO_OFF + a_off1);

        // issue next stage AFTER the A-LDSM burst (fills their latency shadow,
        // keeps STS out of the LDSM front-end window)
        if (st + NSTAGE - 1 < TOTSTEPS) issue(st + NSTAGE - 1);
        CP_COMMIT();

#pragma unroll
        for (int gp = 0; gp < 4; gp++) {
            uint32_t bh[4], bl[4];
            ldsm4(bh, sbase + B_HI_OFF + b_base + gp * 512);
            ldsm4(bl, sbase + B_LO_OFF + b_base + gp * 512);
#pragma unroll
            for (int g2 = 0; g2 < 2; g2++) {
                uint32_t bh0 = bh[2 * g2], bh1 = bh[2 * g2 + 1];
                uint32_t bl0 = bl[2 * g2], bl1 = bl[2 * g2 + 1];
#pragma unroll
                for (int mt = 0; mt < 2; mt++) {
                    float* c = acc[mt][gp * 2 + g2];
                    mma16816(c, Ah[mt], bh0, bh1);
                    mma16816(c, Ah[mt], bl0, bl1);
                    mma16816(c, Al[mt], bh0, bh1);
                }
            }
        }

        if ((st & (NSTEPS - 1)) == NSTEPS - 1) {
            // ---- N-tile epilogue: online softmax (warp-local, 64-col slice) ----
            int nt = st >> 5;
#pragma unroll
            for (int mt = 0; mt < 2; mt++)
#pragma unroll
                for (int h = 0; h < 2; h++) {
                    float r = __int_as_float(0xff800000);
#pragma unroll
                    for (int g = 0; g < 8; g++)
                        r = fmaxf(r, fmaxf(acc[mt][g][2 * h], acc[mt][g][2 * h + 1]));
                    r = fmaxf(r, __shfl_xor_sync(0xFFFFFFFFu, r, 1));
                    r = fmaxf(r, __shfl_xor_sync(0xFFFFFFFFu, r, 2));
                    float mn = fmaxf(m_run[mt][h], r);
                    float sc = __expf(m_run[mt][h] - mn);
                    Zp[mt][h] *= sc; Ap[mt][h] *= sc;
                    m_run[mt][h] = mn;
                }
            const float2* yrow = (const float2*)(yb + nt * TILE_N + warpN * 64);
#pragma unroll
            for (int g = 0; g < 8; g++) {
                float2 yv = __ldg(&yrow[g * 4 + (lane & 3)]);
#pragma unroll
                for (int mt = 0; mt < 2; mt++)
#pragma unroll
                    for (int h = 0; h < 2; h++) {
                        float e0 = __expf(acc[mt][g][2 * h]     - m_run[mt][h]);
                        float e1 = __expf(acc[mt][g][2 * h + 1] - m_run[mt][h]);
                        Zp[mt][h] += e0 + e1;
                        Ap[mt][h] += e0 * yv.x + e1 * yv.y;
                        acc[mt][g][2 * h] = 0.f;
                        acc[mt][g][2 * h + 1] = 0.f;
                    }
            }
        }
    }

    // ---- final reductions: lanes within quad, then across 4 warpN warps ----
#pragma unroll
    for (int mt = 0; mt < 2; mt++)
#pragma unroll
        for (int h = 0; h < 2; h++) {
            float z = Zp[mt][h], a = Ap[mt][h];
            z += __shfl_xor_sync(0xFFFFFFFFu, z, 1);
            z += __shfl_xor_sync(0xFFFFFFFFu, z, 2);
            a += __shfl_xor_sync(0xFFFFFFFFu, a, 1);
            a += __shfl_xor_sync(0xFFFFFFFFu, a, 2);
            Zp[mt][h] = z; Ap[mt][h] = a;
        }
    __syncthreads();
    float* msm  = (float*)smem;            // 128*4
    float* zsm  = msm + 512;
    float* asm2 = msm + 1024;
    if ((lane & 3) == 0) {
#pragma unroll
        for (int mt = 0; mt < 2; mt++)
#pragma unroll
            for (int h = 0; h < 2; h++) {
                int row = warpM * 32 + mt * 16 + (lane >> 2) + h * 8;
                int i = row * 4 + warpN;
                msm[i] = m_run[mt][h];
                zsm[i] = Zp[mt][h];
                asm2[i] = Ap[mt][h];
            }
    }
    __syncthreads();
    if (tid < TILE_M) {
        float m0 = msm[tid * 4], m1 = msm[tid * 4 + 1];
        float m2 = msm[tid * 4 + 2], m3 = msm[tid * 4 + 3];
        float mstar = fmaxf(fmaxf(m0, m1), fmaxf(m2, m3));
        float e0 = __expf(m0 - mstar), e1 = __expf(m1 - mstar);
        float e2 = __expf(m2 - mstar), e3 = __expf(m3 - mstar);
        float Z = zsm[tid * 4] * e0 + zsm[tid * 4 + 1] * e1
                + zsm[tid * 4 + 2] * e2 + zsm[tid * 4 + 3] * e3;
        float A = asm2[tid * 4] * e0 + asm2[tid * 4 + 1] * e1
                + asm2[tid * 4 + 2] * e2 + asm2[tid * 4 + 3] * e3;
        out[(size_t)b * LL + ltile * TILE_M + tid] = A / Z + __ldg(fc_b);
    }
}

// ---------------- host ----------------
extern "C" void kernel_launch(void* const* d_in, const int* in_sizes, int n_in,
                              void* d_out, int out_size) {
    const float* x    = (const float*)d_in[0];
    const float* q    = (const float*)d_in[1];
    const float* fc_w = (const float*)d_in[2];
    const float* fc_b = (const float*)d_in[3];
    float* out = (float*)d_out;

    prep_kernel<<<(BB * TT + LL) / 8, 256>>>(x, q, fc_w);

    cudaFuncSetAttribute(attn_kernel, cudaFuncAttributeMaxDynamicSharedMemorySize, SMEM_TOTAL);
    attn_kernel<<<dim3(LL / TILE_M, BB), NTHREADS, SMEM_TOTAL>>>(fc_b, out);
}

// round 17
// speedup vs baseline: 2.2660x; 1.0608x over previous
#include <cuda_runtime.h>
#include <cuda_bf16.h>
#include <cstdint>

#define BB 16
#define TT 4096
#define DD 512
#define LL 1024

#define TILE_M 128
#define TILE_N 256
#define KSTEP 16
#define NSTEPS (DD / KSTEP)          // 32 k-steps per N-tile
#define NTILES (TT / TILE_N)         // 16
#define TOTSTEPS (NSTEPS * NTILES)   // 512
#define NSTAGE 4

#define A_HI_OFF 0
#define A_LO_OFF 4096
#define B_HI_OFF 8192
#define B_LO_OFF 16384
#define STAGE_BYTES 24576
#define SMEM_TOTAL (NSTAGE * STAGE_BYTES)   // 98304

#define NTHREADS 512

// XOR swizzle: row stride 32B, 16B chunk index XORed with bit2 of row.
#define SWZ(row, chunk) ((uint32_t)((row) * 32 + (((chunk) ^ (((row) >> 2) & 1)) << 4)))

__device__ __nv_bfloat16 g_xh[BB * TT * DD];   // 64 MB
__device__ __nv_bfloat16 g_xl[BB * TT * DD];   // 64 MB
__device__ __nv_bfloat16 g_qh[LL * DD];
__device__ __nv_bfloat16 g_ql[LL * DD];
__device__ float g_y[BB * TT];

// ---------------- PTX helpers ----------------
__device__ __forceinline__ uint32_t smem_u32(const void* p) {
    uint32_t a;
    asm("{ .reg .u64 t; cvta.to.shared.u64 t, %1; cvt.u32.u64 %0, t; }" : "=r"(a) : "l"(p));
    return a;
}
__device__ __forceinline__ void cp16(uint32_t dst, const void* src) {
    asm volatile("cp.async.cg.shared.global [%0], [%1], 16;" :: "r"(dst), "l"(src));
}
#define CP_COMMIT() asm volatile("cp.async.commit_group;" ::: "memory")
#define CP_WAIT2()  asm volatile("cp.async.wait_group 2;" ::: "memory")

__device__ __forceinline__ void ldsm4(uint32_t* r, uint32_t addr) {
    asm volatile("ldmatrix.sync.aligned.m8n8.x4.shared.b16 {%0,%1,%2,%3}, [%4];"
                 : "=r"(r[0]), "=r"(r[1]), "=r"(r[2]), "=r"(r[3]) : "r"(addr));
}
__device__ __forceinline__ void mma16816(float* c, const uint32_t* a, uint32_t b0, uint32_t b1) {
    asm volatile(
        "mma.sync.aligned.m16n8k16.row.col.f32.bf16.bf16.f32 "
        "{%0,%1,%2,%3}, {%4,%5,%6,%7}, {%8,%9}, {%0,%1,%2,%3};"
        : "+f"(c[0]), "+f"(c[1]), "+f"(c[2]), "+f"(c[3])
        : "r"(a[0]), "r"(a[1]), "r"(a[2]), "r"(a[3]), "r"(b0), "r"(b1));
}

// ---------------- precompute: bf16 hi/lo split of x and q, plus y ----------------
// Streaming hints: zero-reuse pass, keep it out of L2's way (__ldcs / __stcs).
__global__ __launch_bounds__(256) void prep_kernel(const float* __restrict__ x,
                                                   const float* __restrict__ q,
                                                   const float* __restrict__ fc_w) {
    int wrow = blockIdx.x * 8 + (threadIdx.x >> 5);
    int lane = threadIdx.x & 31;
    bool is_x = wrow < BB * TT;
    const float* src = is_x ? (x + (size_t)wrow * DD)
                            : (q + (size_t)(wrow - BB * TT) * DD);
    __nv_bfloat16* dh = is_x ? (g_xh + (size_t)wrow * DD)
                             : (g_qh + (size_t)(wrow - BB * TT) * DD);
    __nv_bfloat16* dl = is_x ? (g_xl + (size_t)wrow * DD)
                             : (g_ql + (size_t)(wrow - BB * TT) * DD);
    float s = 0.f;
#pragma unroll
    for (int c = 0; c < 4; c++) {
        int idx = c * 128 + lane * 4;
        float4 v = __ldcs((const float4*)(src + idx));
        if (is_x) {
            float4 w = *(const float4*)(fc_w + idx);   // fc_w reused by all blocks: keep cached
            s += v.x * w.x + v.y * w.y + v.z * w.z + v.w * w.w;
        }
        __nv_bfloat16 hx = __float2bfloat16(v.x), hy = __float2bfloat16(v.y);
        __nv_bfloat16 hz = __float2bfloat16(v.z), hw = __float2bfloat16(v.w);
        __nv_bfloat162 h01, h23, l01, l23;
        h01.x = hx; h01.y = hy; h23.x = hz; h23.y = hw;
        l01.x = __float2bfloat16(v.x - __bfloat162float(hx));
        l01.y = __float2bfloat16(v.y - __bfloat162float(hy));
        l23.x = __float2bfloat16(v.z - __bfloat162float(hz));
        l23.y = __float2bfloat16(v.w - __bfloat162float(hw));
        uint2 ph = make_uint2(*(uint32_t*)&h01, *(uint32_t*)&h23);
        uint2 pl = make_uint2(*(uint32_t*)&l01, *(uint32_t*)&l23);
        __stcs((uint2*)(dh + idx), ph);
        __stcs((uint2*)(dl + idx), pl);
    }
    if (is_x) {
#pragma unroll
        for (int o = 16; o; o >>= 1) s += __shfl_xor_sync(0xFFFFFFFFu, s, o);
        if (lane == 0) g_y[wrow] = s;
    }
}

// ---------------- main kernel: exact R6 champion (16 warps 4Mx4N, 4-stage pipe) ----------------
__global__ __launch_bounds__(NTHREADS, 1) void attn_kernel(const float* __restrict__ fc_b,
                                                           float* __restrict__ out) {
    extern __shared__ char smem[];
    uint32_t sb = smem_u32(smem);
    int tid = threadIdx.x, wid = tid >> 5, lane = tid & 31;
    int warpM = wid & 3, warpN = wid >> 2;      // 4 x 4 warps
    int ltile = blockIdx.x, b = blockIdx.y;

    const __nv_bfloat16* qh = g_qh + (size_t)(ltile * TILE_M) * DD;
    const __nv_bfloat16* ql = g_ql + (size_t)(ltile * TILE_M) * DD;
    const __nv_bfloat16* xh = g_xh + (size_t)b * TT * DD;
    const __nv_bfloat16* xl = g_xl + (size_t)b * TT * DD;
    const float* yb = g_y + b * TT;

    // ---- per-thread load assignment: 1 A chunk + 2 B chunks (16B each), swizzled dst ----
    int ac = tid & 255;
    int a_row = ac >> 1, a_half = ac & 1;
    uint32_t a_dst = (tid < 256 ? A_HI_OFF : A_LO_OFF) + SWZ(a_row, a_half);
    const __nv_bfloat16* a_srcbase = (tid < 256 ? qh : ql) + (size_t)a_row * DD + a_half * 8;
    int b_row = tid >> 1, b_half = tid & 1;
    uint32_t b_dst = SWZ(b_row, b_half);
    size_t b_rowoff = (size_t)b_row * DD + b_half * 8;

    // ---- ldmatrix lane offsets ----
    int a_r0 = warpM * 32 + (lane & 15);
    uint32_t a_off0 = SWZ(a_r0, lane >> 4);
    uint32_t a_off1 = SWZ(a_r0 + 16, lane >> 4);
    int q4 = lane >> 3;
    int b_r0 = warpN * 64 + ((q4 >> 1) & 1) * 8 + (lane & 7);
    uint32_t b_base = SWZ(b_r0, q4 & 1);

    // ---- accumulators + softmax state ----
    float acc[2][8][4];
#pragma unroll
    for (int mt = 0; mt < 2; mt++)
#pragma unroll
        for (int g = 0; g < 8; g++)
#pragma unroll
            for (int i = 0; i < 4; i++) acc[mt][g][i] = 0.f;
    float m_run[2][2], Zp[2][2], Ap[2][2];
#pragma unroll
    for (int mt = 0; mt < 2; mt++)
#pragma unroll
        for (int h = 0; h < 2; h++) {
            m_run[mt][h] = __int_as_float(0xff800000);
            Zp[mt][h] = 0.f; Ap[mt][h] = 0.f;
        }

    auto issue = [&](int s) {
        int nt = s >> 5, kc = s & 31;
        int k0 = kc * KSTEP;
        uint32_t sbase = sb + (s & (NSTAGE - 1)) * STAGE_BYTES;
        cp16(sbase + a_dst, a_srcbase + k0);
        size_t bsrc = (size_t)(nt * TILE_N) * DD + k0 + b_rowoff;
        cp16(sbase + B_HI_OFF + b_dst, xh + bsrc);
        cp16(sbase + B_LO_OFF + b_dst, xl + bsrc);
    };

    for (int s = 0; s < NSTAGE - 1; s++) { issue(s); CP_COMMIT(); }

    for (int st = 0; st < TOTSTEPS; st++) {
        CP_WAIT2();
        __syncthreads();
        if (st + NSTAGE - 1 < TOTSTEPS) issue(st + NSTAGE - 1);
        CP_COMMIT();

        uint32_t sbase = sb + (st & (NSTAGE - 1)) * STAGE_BYTES;
        uint32_t Ah[2][4], Al[2][4];
        ldsm4(Ah[0], sbase + A_HI_OFF + a_off0);
        ldsm4(Ah[1], sbase + A_HI_OFF + a_off1);
        ldsm4(Al[0], sbase + A_LO_OFF + a_off0);
        ldsm4(Al[1], sbase + A_LO_OFF + a_off1);
#pragma unroll
        for (int gp = 0; gp < 4; gp++) {
            uint32_t bh[4], bl[4];
            ldsm4(bh, sbase + B_HI_OFF + b_base + gp * 512);
            ldsm4(bl, sbase + B_LO_OFF + b_base + gp * 512);
#pragma unroll
            for (int g2 = 0; g2 < 2; g2++) {
                uint32_t bh0 = bh[2 * g2], bh1 = bh[2 * g2 + 1];
                uint32_t bl0 = bl[2 * g2], bl1 = bl[2 * g2 + 1];
#pragma unroll
                for (int mt = 0; mt < 2; mt++) {
                    float* c = acc[mt][gp * 2 + g2];
                    mma16816(c, Ah[mt], bh0, bh1);
                    mma16816(c, Ah[mt], bl0, bl1);
                    mma16816(c, Al[mt], bh0, bh1);
                }
            }
        }

        if ((st & (NSTEPS - 1)) == NSTEPS - 1) {
            // ---- N-tile epilogue: online softmax (warp-local, 64-col slice) ----
            int nt = st >> 5;
#pragma unroll
            for (int mt = 0; mt < 2; mt++)
#pragma unroll
                for (int h = 0; h < 2; h++) {
                    float r = __int_as_float(0xff800000);
#pragma unroll
                    for (int g = 0; g < 8; g++)
                        r = fmaxf(r, fmaxf(acc[mt][g][2 * h], acc[mt][g][2 * h + 1]));
                    r = fmaxf(r, __shfl_xor_sync(0xFFFFFFFFu, r, 1));
                    r = fmaxf(r, __shfl_xor_sync(0xFFFFFFFFu, r, 2));
                    float mn = fmaxf(m_run[mt][h], r);
                    float sc = __expf(m_run[mt][h] - mn);
                    Zp[mt][h] *= sc; Ap[mt][h] *= sc;
                    m_run[mt][h] = mn;
                }
            const float2* yrow = (const float2*)(yb + nt * TILE_N + warpN * 64);
#pragma unroll
            for (int g = 0; g < 8; g++) {
                float2 yv = __ldg(&yrow[g * 4 + (lane & 3)]);
#pragma unroll
                for (int mt = 0; mt < 2; mt++)
#pragma unroll
                    for (int h = 0; h < 2; h++) {
                        float e0 = __expf(acc[mt][g][2 * h]     - m_run[mt][h]);
                        float e1 = __expf(acc[mt][g][2 * h + 1] - m_run[mt][h]);
                        Zp[mt][h] += e0 + e1;
                        Ap[mt][h] += e0 * yv.x + e1 * yv.y;
                        acc[mt][g][2 * h] = 0.f;
                        acc[mt][g][2 * h + 1] = 0.f;
                    }
            }
        }
    }

    // ---- final reductions: lanes within quad, then across 4 warpN warps ----
#pragma unroll
    for (int mt = 0; mt < 2; mt++)
#pragma unroll
        for (int h = 0; h < 2; h++) {
            float z = Zp[mt][h], a = Ap[mt][h];
            z += __shfl_xor_sync(0xFFFFFFFFu, z, 1);
            z += __shfl_xor_sync(0xFFFFFFFFu, z, 2);
            a += __shfl_xor_sync(0xFFFFFFFFu, a, 1);
            a += __shfl_xor_sync(0xFFFFFFFFu, a, 2);
            Zp[mt][h] = z; Ap[mt][h] = a;
        }
    __syncthreads();
    float* msm  = (float*)smem;            // 128*4
    float* zsm  = msm + 512;
    float* asm2 = msm + 1024;
    if ((lane & 3) == 0) {
#pragma unroll
        for (int mt = 0; mt < 2; mt++)
#pragma unroll
            for (int h = 0; h < 2; h++) {
                int row = warpM * 32 + mt * 16 + (lane >> 2) + h * 8;
                int i = row * 4 + warpN;
                msm[i] = m_run[mt][h];
                zsm[i] = Zp[mt][h];
                asm2[i] = Ap[mt][h];
            }
    }
    __syncthreads();
    if (tid < TILE_M) {
        float m0 = msm[tid * 4], m1 = msm[tid * 4 + 1];
        float m2 = msm[tid * 4 + 2], m3 = msm[tid * 4 + 3];
        float mstar = fmaxf(fmaxf(m0, m1), fmaxf(m2, m3));
        float e0 = __expf(m0 - mstar), e1 = __expf(m1 - mstar);
        float e2 = __expf(m2 - mstar), e3 = __expf(m3 - mstar);
        float Z = zsm[tid * 4] * e0 + zsm[tid * 4 + 1] * e1
                + zsm[tid * 4 + 2] * e2 + zsm[tid * 4 + 3] * e3;
        float A = asm2[tid * 4] * e0 + asm2[tid * 4 + 1] * e1
                + asm2[tid * 4 + 2] * e2 + asm2[tid * 4 + 3] * e3;
        out[(size_t)b * LL + ltile * TILE_M + tid] = A / Z + __ldg(fc_b);
    }
}

// ---------------- host ----------------
extern "C" void kernel_launch(void* const* d_in, const int* in_sizes, int n_in,
                              void* d_out, int out_size) {
    const float* x    = (const float*)d_in[0];
    const float* q    = (const float*)d_in[1];
    const float* fc_w = (const float*)d_in[2];
    const float* fc_b = (const float*)d_in[3];
    float* out = (float*)d_out;

    prep_kernel<<<(BB * TT + LL) / 8, 256>>>(x, q, fc_w);

    cudaFuncSetAttribute(attn_kernel, cudaFuncAttributeMaxDynamicSharedMemorySize, SMEM_TOTAL);
    attn_kernel<<<dim3(LL / TILE_M, BB), NTHREADS, SMEM_TOTAL>>>(fc_b, out);
}